// round 15
// baseline (speedup 1.0000x reference)
#include <cuda_runtime.h>
#include <math.h>

#define BB 8
#define SN 512
#define SIDX 256
#define DF 768
#define NH 12
#define HD 64
#define PJ 256
#define HID 128
#define VOC 16384
#define KTOP 20
#define KVN 1536

#define ASTR 20     // A smem row stride (m-major, 16 k + pad)
#define BSTR1 20    // B smem row stride, BT=1 ([n][k])
#define BSTR0 68    // B smem row stride, BT=0 ([k][n])

// ---------------- scratch (static device globals; no allocations) ------------
__device__ float g_emb[BB*SN*DF];
__device__ float g_q  [BB*SIDX*DF];
__device__ float g_kv [BB*SN*KVN];
__device__ float g_s  [BB*NH*SIDX*SN];
__device__ float g_o  [BB*SIDX*DF];
__device__ float g_mha[BB*SIDX*DF];
__device__ float g_xp [BB*SN*PJ];
__device__ float g_x1 [BB*SN*768];
__device__ float g_h1 [BB*SN*HID];
__device__ float g_x2 [BB*SN*384];
__device__ float g_h2 [BB*SN*HID];
__device__ float g_e  [BB*SN*DF];
__device__ float g_sq [BB*SN];
__device__ float g_w  [BB*SN*SN];
__device__ unsigned char g_mk[BB*SN*SN];
__device__ float g_dsi[BB*SN];
__device__ float g_A  [BB*SN*SN];
__device__ float g_Xa [BB*SN*SN];
__device__ float g_Xb [BB*SN*SN];
__device__ float g_T  [BB*SN*SN];
__device__ float g_w1r[HID*768];
__device__ float g_w2r[HID*384];

// ---------------- unified tensor-core GEMM (split-tf32, cp.async) -------------
// R14 tiling (128 thr, 4 warps, 64x32 warp tile, 2:1 MMA:LDS) + R15: 3 CTAs/SM
// (12 warps/SM) to cover MMA/LDS latency; regs 158 <= 170 cap, smem 3x31KB OK.
// C = epi( A(MxK) * op(B) ) ; BT=1: B is [N,K] (C=A*B^T), BT=0: B is [K,N]
// CTA tile 128x64, K-slab 16. Requires M%128==0, N%64==0, K%16==0.
// EPI: 0 scale  1 +bias  2 conv+bn+relu  3 gaussian-W
//      4 scaled-newton: C = gamma_iter * (2*X - acc), gamma from Chebyshev
//        composition recurrence t_{k+1}=2t_k^2-1, t_1=2*mu^2-1, mu=(1+eps)/alpha.
struct GemmP {
    const float* A; const float* B; float* C;
    int N, K, lda, ldb, ldc, zdiv;
    long sA1, sA2, sB1, sB2, sC1, sC2, sP0;
    float scale;
    const float* p0; const float* p1; const float* p2;
    const float* alp; int iter;
};

__device__ __forceinline__ float tf32hi(float x) {
    return __uint_as_float(__float_as_uint(x) & 0xFFFFE000u);
}
__device__ __forceinline__ void mma8(float* d, const unsigned* a, const unsigned* b) {
    asm volatile("mma.sync.aligned.m16n8k8.row.col.f32.tf32.tf32.f32 "
        "{%0,%1,%2,%3}, {%4,%5,%6,%7}, {%8,%9}, {%0,%1,%2,%3};"
        : "+f"(d[0]), "+f"(d[1]), "+f"(d[2]), "+f"(d[3])
        : "r"(a[0]), "r"(a[1]), "r"(a[2]), "r"(a[3]), "r"(b[0]), "r"(b[1]));
}
#define CPA16(dst, src) asm volatile("cp.async.ca.shared.global [%0], [%1], 16;" \
                                     :: "r"(dst), "l"(src))
#define CPCOMMIT()      asm volatile("cp.async.commit_group;")
#define CPWAIT0()       asm volatile("cp.async.wait_group 0;" ::: "memory")

template<int EPI, int BT>
__global__ void __launch_bounds__(128, 3) tgemm_k(GemmP p) {
    __shared__ float As[2][128*ASTR];
    __shared__ float Bs[2][1280];
    int z  = blockIdx.z;
    int zb = z / p.zdiv, zr = z % p.zdiv;
    const float* Ap = p.A + zb * p.sA1 + (long)zr * p.sA2;
    const float* Bp = p.B + zb * p.sB1 + (long)zr * p.sB2;
    float*       Cp = p.C + zb * p.sC1 + (long)zr * p.sC2;
    int bm = blockIdx.y * 128, bn = blockIdx.x * 64;
    int tid = threadIdx.x;
    int warp = tid >> 5, lane = tid & 31;
    int g = lane >> 2, t = lane & 3;
    int m0 = (warp >> 1) * 64, n0 = (warp & 1) * 32;

    // loader coords (128 threads)
    int ar  = tid >> 2, akq = (tid & 3) * 4;   // A: 4 f4/thread, rows ar+f*32
    int bkr = tid >> 4, bnc = (tid & 15) * 4;  // B BT=0: 2 f4/thread
    unsigned sA[2] = { (unsigned)__cvta_generic_to_shared(&As[0][0]),
                       (unsigned)__cvta_generic_to_shared(&As[1][0]) };
    unsigned sB[2] = { (unsigned)__cvta_generic_to_shared(&Bs[0][0]),
                       (unsigned)__cvta_generic_to_shared(&Bs[1][0]) };

    float acc[4][4][4];
#pragma unroll
    for (int i = 0; i < 4; i++)
#pragma unroll
        for (int j = 0; j < 4; j++)
#pragma unroll
            for (int r = 0; r < 4; r++) acc[i][j][r] = 0.f;

    int nSlab = p.K >> 4;

    auto issue = [&](int it) {
        int buf = it & 1;
        int k0 = it << 4;
#pragma unroll
        for (int f = 0; f < 4; f++)
            CPA16(sA[buf] + (unsigned)(((ar + f*32)*ASTR + akq) * 4),
                  Ap + (long)(bm + ar + f*32) * p.lda + k0 + akq);
        if (BT) {
#pragma unroll
            for (int f = 0; f < 2; f++)
                CPA16(sB[buf] + (unsigned)(((ar + f*32)*BSTR1 + akq) * 4),
                      Bp + (long)(bn + ar + f*32) * p.ldb + k0 + akq);
        } else {
#pragma unroll
            for (int f = 0; f < 2; f++)
                CPA16(sB[buf] + (unsigned)(((bkr + f*8)*BSTR0 + bnc) * 4),
                      Bp + (long)(k0 + bkr + f*8) * p.ldb + bn + bnc);
        }
        CPCOMMIT();
    };

    issue(0);
    for (int it = 0; it < nSlab; it++) {
        CPWAIT0();
        __syncthreads();
        if (it + 1 < nSlab) issue(it + 1);
        const float* as = As[it & 1];
        const float* bs = Bs[it & 1];
#pragma unroll
        for (int ks = 0; ks < 2; ks++) {
            int kb = ks * 8;
            unsigned ah[4][4], al[4][4];
#pragma unroll
            for (int i = 0; i < 4; i++) {
                int mb = m0 + i*16;
                float r0 = as[(mb + g    )*ASTR + kb + t    ];
                float r1 = as[(mb + 8 + g)*ASTR + kb + t    ];
                float r2 = as[(mb + g    )*ASTR + kb + t + 4];
                float r3 = as[(mb + 8 + g)*ASTR + kb + t + 4];
                float h0 = tf32hi(r0), h1 = tf32hi(r1), h2 = tf32hi(r2), h3 = tf32hi(r3);
                ah[i][0] = __float_as_uint(h0); al[i][0] = __float_as_uint(r0 - h0);
                ah[i][1] = __float_as_uint(h1); al[i][1] = __float_as_uint(r1 - h1);
                ah[i][2] = __float_as_uint(h2); al[i][2] = __float_as_uint(r2 - h2);
                ah[i][3] = __float_as_uint(h3); al[i][3] = __float_as_uint(r3 - h3);
            }
            unsigned bh[4][2], bl[4][2];
#pragma unroll
            for (int j = 0; j < 4; j++) {
                int nb = n0 + j*8 + g;
                float r0, r1;
                if (BT) { r0 = bs[nb*BSTR1 + kb + t];   r1 = bs[nb*BSTR1 + kb + t + 4]; }
                else    { r0 = bs[(kb + t)*BSTR0 + nb]; r1 = bs[(kb + t + 4)*BSTR0 + nb]; }
                float h0 = tf32hi(r0), h1 = tf32hi(r1);
                bh[j][0] = __float_as_uint(h0); bl[j][0] = __float_as_uint(r0 - h0);
                bh[j][1] = __float_as_uint(h1); bl[j][1] = __float_as_uint(r1 - h1);
            }
#pragma unroll
            for (int i = 0; i < 4; i++)
#pragma unroll
                for (int j = 0; j < 4; j++) {
                    mma8(acc[i][j], ah[i], bh[j]);
                    mma8(acc[i][j], ah[i], bl[j]);
                    mma8(acc[i][j], al[i], bh[j]);
                }
        }
        __syncthreads();
    }

    const float* P0 = p.p0;
    if (EPI == 3 || EPI == 4) P0 = p.p0 + zb * p.sP0;
    float gam = 1.f;
    if (EPI == 4) {
        float mu = (1.f + 1e-6f) / p.alp[0];
        float tt = 2.f*mu*mu - 1.f;               // t_1 = T_2(mu)
        for (int q = 0; q < p.iter; q++) tt = 2.f*tt*tt - 1.f;
        float tg = 2.f*tt*tt;
        gam = tg / (tg - 1.f);
    }
#pragma unroll
    for (int i = 0; i < 4; i++)
#pragma unroll
        for (int j = 0; j < 4; j++) {
            int m  = bm + m0 + i*16 + g;
            int n  = bn + n0 + j*8 + 2*t;
            float v0 = acc[i][j][0], v1 = acc[i][j][1];
            float v2 = acc[i][j][2], v3 = acc[i][j][3];
            if (EPI == 0) {
                v0 *= p.scale; v1 *= p.scale; v2 *= p.scale; v3 *= p.scale;
            } else if (EPI == 1) {
                v0 += p.p0[n]; v1 += p.p0[n+1]; v2 += p.p0[n]; v3 += p.p0[n+1];
            } else if (EPI == 2) {
                float g0 = 0.9999950000125f * p.p1[n],   b0 = p.p2[n];
                float g1 = 0.9999950000125f * p.p1[n+1], b1 = p.p2[n+1];
                v0 = fmaxf((v0 + p.p0[n])   * g0 + b0, 0.f);
                v1 = fmaxf((v1 + p.p0[n+1]) * g1 + b1, 0.f);
                v2 = fmaxf((v2 + p.p0[n])   * g0 + b0, 0.f);
                v3 = fmaxf((v3 + p.p0[n+1]) * g1 + b1, 0.f);
            } else if (EPI == 3) {
                float sm0 = P0[m], sm8 = P0[m+8], sn0 = P0[n], sn1 = P0[n+1];
                v0 = expf(-fmaxf(sm0 + sn0 - 2.f*v0, 0.f) * (1.f/1536.f));
                v1 = expf(-fmaxf(sm0 + sn1 - 2.f*v1, 0.f) * (1.f/1536.f));
                v2 = expf(-fmaxf(sm8 + sn0 - 2.f*v2, 0.f) * (1.f/1536.f));
                v3 = expf(-fmaxf(sm8 + sn1 - 2.f*v3, 0.f) * (1.f/1536.f));
            } else if (EPI == 4) {
                v0 = gam * (2.f * P0[(long)m*p.ldc + n]       - v0);
                v1 = gam * (2.f * P0[(long)m*p.ldc + n + 1]   - v1);
                v2 = gam * (2.f * P0[(long)(m+8)*p.ldc + n]   - v2);
                v3 = gam * (2.f * P0[(long)(m+8)*p.ldc + n+1] - v3);
            }
            Cp[(long)m*p.ldc + n]       = v0;
            Cp[(long)m*p.ldc + n + 1]   = v1;
            Cp[(long)(m+8)*p.ldc + n]   = v2;
            Cp[(long)(m+8)*p.ldc + n+1] = v3;
        }
}

// ---------------- elementwise / reduction kernels ----------------------------
__global__ void k_build_emb(const float* ge, const float* ue) {
    long i = (long)blockIdx.x * blockDim.x + threadIdx.x;
    if (i >= (long)BB*SN*DF) return;
    int d = i % DF; long bn = i / DF; int n = bn % SN; int b = (int)(bn / SN);
    float x = (n < SIDX) ? ge[((long)b*SIDX + n)*DF + d]
                         : ue[((long)b*SIDX + (n - SIDX))*DF + d];
    int half = d >> 1;
    float freq = expf((float)(2*half) * (-9.210340371976184f/768.f));
    float arg = (float)n * freq;
    float pe = (d & 1) ? cosf(arg) : sinf(arg);
    g_emb[i] = x + pe;
}

__global__ void k_softmax() {
    long row = blockIdx.x;
    float* r = g_s + row * SN;
    int tid = threadIdx.x;
    __shared__ float red[256];
    float v0 = r[tid], v1 = r[tid+256];
    red[tid] = fmaxf(v0, v1); __syncthreads();
    for (int s = 128; s > 0; s >>= 1) { if (tid < s) red[tid] = fmaxf(red[tid], red[tid+s]); __syncthreads(); }
    float m = red[0]; __syncthreads();
    float e0 = expf(v0 - m), e1 = expf(v1 - m);
    red[tid] = e0 + e1; __syncthreads();
    for (int s = 128; s > 0; s >>= 1) { if (tid < s) red[tid] += red[tid+s]; __syncthreads(); }
    float inv = 1.f / red[0];
    r[tid] = e0 * inv; r[tid+256] = e1 * inv;
}

__global__ void k_addln(const float* lng, const float* lnb) {
    int row = blockIdx.x;
    int b = row >> 8, rr = row & 255;
    float*       u  = g_emb + ((long)b*SN + SIDX + rr) * DF;
    const float* mh = g_mha + ((long)b*SIDX + rr) * DF;
    int tid = threadIdx.x;
    __shared__ float red[256];
    float x[3];
#pragma unroll
    for (int t = 0; t < 3; t++) x[t] = u[tid + t*256] + mh[tid + t*256];
    red[tid] = x[0] + x[1] + x[2]; __syncthreads();
    for (int s = 128; s > 0; s >>= 1) { if (tid < s) red[tid] += red[tid+s]; __syncthreads(); }
    float mean = red[0] * (1.f/768.f); __syncthreads();
    float vs = 0.f;
#pragma unroll
    for (int t = 0; t < 3; t++) { float d = x[t] - mean; vs += d*d; }
    red[tid] = vs; __syncthreads();
    for (int s = 128; s > 0; s >>= 1) { if (tid < s) red[tid] += red[tid+s]; __syncthreads(); }
    float inv = rsqrtf(red[0] * (1.f/768.f) + 1e-5f);
#pragma unroll
    for (int t = 0; t < 3; t++) {
        int d = tid + t*256;
        u[d] = (x[t] - mean) * inv * lng[d] + lnb[d];
    }
}

__global__ void k_wprep(const float* c1w, const float* c2w) {
    int i = blockIdx.x * blockDim.x + threadIdx.x;
    if (i < 128*768) {
        int c = i / 768, r = i % 768, k = r / 256, ci = r % 256;
        g_w1r[i] = c1w[(c*256 + ci)*3 + k];
    } else if (i < 128*768 + 128*384) {
        int j = i - 128*768;
        int c = j / 384, r = j % 384, k = r / 128, ci = r % 128;
        g_w2r[j] = c2w[(c*128 + ci)*3 + k];
    }
}

__global__ void k_im2col1() {
    long i = (long)blockIdx.x * blockDim.x + threadIdx.x;
    if (i >= (long)BB*SN*768) return;
    int d = i % 768; long bl = i / 768; int l = bl % SN; int b = (int)(bl / SN);
    int k = d / 256, ci = d % 256;
    int src = l + k - 1;
    g_x1[i] = (src >= 0 && src < SN) ? g_xp[((long)b*SN + src)*PJ + ci] : 0.f;
}

__global__ void k_im2col2() {
    long i = (long)blockIdx.x * blockDim.x + threadIdx.x;
    if (i >= (long)BB*SN*384) return;
    int d = i % 384; long bl = i / 384; int l = bl % SN; int b = (int)(bl / SN);
    int k = d / 128, ci = d % 128;
    int src = l + k - 1;
    g_x2[i] = (src >= 0 && src < SN) ? g_h1[((long)b*SN + src)*HID + ci] : 0.f;
}

__global__ void k_sigma_e(const float* ow, const float* ob) {
    int row = blockIdx.x;
    int tid = threadIdx.x;
    __shared__ float red[256];
    float part = (tid < HID) ? g_h2[(long)row*HID + tid] * ow[tid] : 0.f;
    red[tid] = part; __syncthreads();
    for (int s = 128; s > 0; s >>= 1) { if (tid < s) red[tid] += red[tid+s]; __syncthreads(); }
    float sig = red[0] + ob[0]; __syncthreads();
    float inv = 1.f / (sig + 1e-6f);
    const float* er = g_emb + (long)row*DF;
    float*       eo = g_e   + (long)row*DF;
    float ss = 0.f;
#pragma unroll
    for (int t = 0; t < 3; t++) {
        float e = er[tid + t*256] * inv;
        eo[tid + t*256] = e;
        ss += e*e;
    }
    red[tid] = ss; __syncthreads();
    for (int s = 128; s > 0; s >>= 1) { if (tid < s) red[tid] += red[tid+s]; __syncthreads(); }
    if (tid == 0) g_sq[row] = red[0];
}

__global__ void k_topk() {
    int row = blockIdx.x * (blockDim.x >> 5) + (threadIdx.x >> 5);
    int lane = threadIdx.x & 31;
    if (row >= BB*SN) return;
    const float* w = g_w + (long)row * SN;
    unsigned char* mk = g_mk + (long)row * SN;
    for (int j = lane; j < SN/4; j += 32) ((unsigned int*)mk)[j] = 0u;
    __syncwarp();
    float v[16];
#pragma unroll
    for (int j = 0; j < 16; j++) v[j] = w[lane + j*32];
    for (int t = 0; t < KTOP; t++) {
        float bm = -1.f; int bj = 0;
#pragma unroll
        for (int j = 0; j < 16; j++) {
            if (v[j] > bm) { bm = v[j]; bj = j; }
        }
        int bidx = lane + bj*32;
#pragma unroll
        for (int s = 16; s > 0; s >>= 1) {
            float om = __shfl_xor_sync(0xffffffffu, bm, s);
            int oi = __shfl_xor_sync(0xffffffffu, bidx, s);
            if (om > bm || (om == bm && oi < bidx)) { bm = om; bidx = oi; }
        }
        if ((bidx & 31) == lane) v[bidx >> 5] = -1.f;
        if (lane == 0) mk[bidx] = 1;
        __syncwarp();
    }
}

__global__ void k_degree() {
    int row = blockIdx.x;
    int b = row >> 9, n = row & 511;
    float* w = g_w + (long)row*SN;
    const unsigned char* mrow = g_mk + (long)row*SN;
    int tid = threadIdx.x;
    __shared__ float red[256];
    float s = 0.f;
    for (int m = tid; m < SN; m += 256) {
        int on = mrow[m] | g_mk[((long)(b*SN + m))*SN + n];
        float val = on ? w[m] : 0.f;
        w[m] = val;
        s += val;
    }
    red[tid] = s; __syncthreads();
    for (int st = 128; st > 0; st >>= 1) { if (tid < st) red[tid] += red[tid+st]; __syncthreads(); }
    if (tid == 0) g_dsi[row] = rsqrtf(red[0] + 1e-6f);
}

// Build A = (1+eps)I - alpha*S, and Chebyshev-optimal X1 = c0*I + c1*A:
// E1(l) = 1 - c0 l - c1 l^2 = T_2(muhat(l))/T_2(mu) on [1+eps-alpha, 1+eps+alpha].
__global__ void k_buildA(const float* alpha) {
    long i = (long)blockIdx.x * blockDim.x + threadIdx.x;
    if (i >= (long)BB*SN*SN) return;
    int m = (int)(i % SN); long t = i / SN; int n = (int)(t % SN); int b = (int)(t / SN);
    float a = alpha[0];
    float Sg = 2.f * (1.f + 1e-6f);
    float Dg = 2.f * a;
    float den = 2.f * Sg * Sg - Dg * Dg;
    float c0 = 8.f * Sg / den, c1 = -8.f / den;
    float s = g_dsi[b*SN+n] * g_w[i] * g_dsi[b*SN+m];
    float A = ((n==m) ? 1.f + 1e-6f : 0.f) - a * s;
    g_A[i] = A;
    g_Xa[i] = ((n==m) ? c0 : 0.f) + c1 * A;
}

__global__ void k_scatter(const int* labels, const float* X, float* out) {
    int b = blockIdx.z;
    int m = blockIdx.y;
    int n = blockIdx.x * 128 + threadIdx.x;
    int lab = labels[b*SN + m];
    if (lab >= VOC) return;
    float v = X[((long)(b*SN + m))*SN + n];    // symmetric: prop[b,n,m]
    atomicAdd(out + ((long)(b*SN + n))*VOC + lab, v);
}

// ---------------- host side ---------------------------------------------------
static void run_tg(int epi, int bt, const GemmP& p, int M, int Z) {
    dim3 g(p.N / 64, M / 128, Z);
    dim3 b(128);
    if (epi == 0 && bt == 1) tgemm_k<0,1><<<g,b>>>(p);
    else if (epi == 0 && bt == 0) tgemm_k<0,0><<<g,b>>>(p);
    else if (epi == 1 && bt == 1) tgemm_k<1,1><<<g,b>>>(p);
    else if (epi == 2 && bt == 1) tgemm_k<2,1><<<g,b>>>(p);
    else if (epi == 3 && bt == 1) tgemm_k<3,1><<<g,b>>>(p);
    else if (epi == 4 && bt == 0) tgemm_k<4,0><<<g,b>>>(p);
}

extern "C" void kernel_launch(void* const* d_in, const int* in_sizes, int n_in,
                              void* d_out, int out_size) {
    const float* ge    = (const float*)d_in[0];
    const float* ue    = (const float*)d_in[1];
    const float* hs    = (const float*)d_in[2];
    const int*   lab   = (const int*)  d_in[3];
    const float* inw   = (const float*)d_in[4];
    const float* inb   = (const float*)d_in[5];
    const float* outw  = (const float*)d_in[6];
    const float* outb  = (const float*)d_in[7];
    const float* lng   = (const float*)d_in[8];
    const float* lnb   = (const float*)d_in[9];
    const float* pw    = (const float*)d_in[10];
    const float* pb    = (const float*)d_in[11];
    const float* c1w   = (const float*)d_in[12];
    const float* c1b   = (const float*)d_in[13];
    const float* bn1g  = (const float*)d_in[14];
    const float* bn1b  = (const float*)d_in[15];
    const float* c2w   = (const float*)d_in[16];
    const float* c2b   = (const float*)d_in[17];
    const float* bn2g  = (const float*)d_in[18];
    const float* bn2b  = (const float*)d_in[19];
    const float* ow    = (const float*)d_in[20];
    const float* ob    = (const float*)d_in[21];
    const float* alpha = (const float*)d_in[22];
    float* out = (float*)d_out;

    void* vp;
    cudaGetSymbolAddress(&vp, g_emb); float* p_emb = (float*)vp;
    cudaGetSymbolAddress(&vp, g_q);   float* p_q   = (float*)vp;
    cudaGetSymbolAddress(&vp, g_kv);  float* p_kv  = (float*)vp;
    cudaGetSymbolAddress(&vp, g_s);   float* p_s   = (float*)vp;
    cudaGetSymbolAddress(&vp, g_o);   float* p_o   = (float*)vp;
    cudaGetSymbolAddress(&vp, g_mha); float* p_mha = (float*)vp;
    cudaGetSymbolAddress(&vp, g_xp);  float* p_xp  = (float*)vp;
    cudaGetSymbolAddress(&vp, g_x1);  float* p_x1  = (float*)vp;
    cudaGetSymbolAddress(&vp, g_h1);  float* p_h1  = (float*)vp;
    cudaGetSymbolAddress(&vp, g_x2);  float* p_x2  = (float*)vp;
    cudaGetSymbolAddress(&vp, g_h2);  float* p_h2  = (float*)vp;
    cudaGetSymbolAddress(&vp, g_e);   float* p_e   = (float*)vp;
    cudaGetSymbolAddress(&vp, g_sq);  float* p_sq  = (float*)vp;
    cudaGetSymbolAddress(&vp, g_w);   float* p_w   = (float*)vp;
    cudaGetSymbolAddress(&vp, g_A);   float* p_A   = (float*)vp;
    cudaGetSymbolAddress(&vp, g_Xa);  float* p_Xa  = (float*)vp;
    cudaGetSymbolAddress(&vp, g_Xb);  float* p_Xb  = (float*)vp;
    cudaGetSymbolAddress(&vp, g_T);   float* p_T   = (float*)vp;
    cudaGetSymbolAddress(&vp, g_w1r); float* p_w1r = (float*)vp;
    cudaGetSymbolAddress(&vp, g_w2r); float* p_w2r = (float*)vp;

    // 1. emb = concat + PE ; weight reshapes
    k_build_emb<<<(BB*SN*DF + 255)/256, 256>>>(ge, ue);
    k_wprep<<<(128*768 + 128*384)/256, 256>>>(c1w, c2w);

    GemmP p;
    p.zdiv = 1; p.scale = 1.f;
    p.sA1 = p.sA2 = p.sB1 = p.sB2 = p.sC1 = p.sC2 = p.sP0 = 0;
    p.p0 = p.p1 = p.p2 = 0; p.alp = alpha; p.iter = 0;

    // 2. Q = u @ wq^T + bq   (batched over b, M=256 per batch)
    p.A = p_emb + SIDX*DF; p.sA1 = (long)SN*DF; p.lda = DF;
    p.B = inw;             p.ldb = DF;  p.sB1 = 0;
    p.C = p_q;  p.sC1 = (long)SIDX*DF; p.ldc = DF;
    p.N = DF; p.K = DF; p.p0 = inb;
    run_tg(1, 1, p, SIDX, BB);
    // 3. [K|V] = hs @ [wk;wv]^T + [bk;bv]  -- fused, N=1536, M=4096
    p.A = hs; p.sA1 = 0; p.lda = DF;
    p.B = inw + DF*DF;  p.C = p_kv; p.sC1 = 0; p.ldc = KVN;
    p.N = KVN; p.p0 = inb + DF;
    run_tg(1, 1, p, BB*SN, 1);

    // 4. scores = Q K^T / 8  (z = b*h, K=64); K lives in g_kv cols [0,768)
    p.zdiv = NH;
    p.A = p_q;  p.sA1 = (long)SIDX*DF;  p.sA2 = HD; p.lda = DF;
    p.B = p_kv; p.sB1 = (long)SN*KVN;   p.sB2 = HD; p.ldb = KVN;
    p.C = p_s;  p.sC1 = (long)NH*SIDX*SN; p.sC2 = (long)SIDX*SN; p.ldc = SN;
    p.N = SN; p.K = HD; p.scale = 0.125f;
    run_tg(0, 1, p, SIDX, BB*NH);
    // 5. softmax
    k_softmax<<<BB*NH*SIDX, 256>>>();
    // 6. o = attn @ V  (BT=0, N=64); V lives in g_kv cols [768,1536)
    p.A = p_s;  p.sA1 = (long)NH*SIDX*SN; p.sA2 = (long)SIDX*SN; p.lda = SN;
    p.B = p_kv + DF; p.sB1 = (long)SN*KVN; p.sB2 = HD; p.ldb = KVN;
    p.C = p_o;  p.sC1 = (long)SIDX*DF; p.sC2 = HD; p.ldc = DF;
    p.N = HD; p.K = SN; p.scale = 1.f;
    run_tg(0, 0, p, SIDX, BB*NH);
    // 7. mha = o @ out_w^T + out_b  (M=2048)
    p.zdiv = 1; p.sA1 = p.sA2 = p.sB1 = p.sB2 = p.sC1 = p.sC2 = 0;
    p.A = p_o; p.lda = DF; p.B = outw; p.ldb = DF;
    p.C = p_mha; p.ldc = DF; p.N = DF; p.K = DF; p.p0 = outb;
    run_tg(1, 1, p, BB*SIDX, 1);
    // 8. u = LN(u + mha)
    k_addln<<<BB*SIDX, 256>>>(lng, lnb);
    // 9. xp = emb @ proj_w^T + proj_b  (M=4096, N=256)
    p.A = p_emb; p.lda = DF; p.B = pw; p.ldb = DF;
    p.C = p_xp; p.ldc = PJ; p.N = PJ; p.K = DF; p.p0 = pb;
    run_tg(1, 1, p, BB*SN, 1);
    // 10. conv1 + bn + relu  (M=4096, N=128, K=768)
    k_im2col1<<<(BB*SN*768 + 255)/256, 256>>>();
    p.A = p_x1; p.lda = 768; p.B = p_w1r; p.ldb = 768;
    p.C = p_h1; p.ldc = HID; p.N = HID; p.K = 768;
    p.p0 = c1b; p.p1 = bn1g; p.p2 = bn1b;
    run_tg(2, 1, p, BB*SN, 1);
    // 11. conv2 + bn + relu  (M=4096, N=128, K=384)
    k_im2col2<<<(BB*SN*384 + 255)/256, 256>>>();
    p.A = p_x2; p.lda = 384; p.B = p_w2r; p.ldb = 384;
    p.C = p_h2; p.ldc = HID; p.N = HID; p.K = 384;
    p.p0 = c2b; p.p1 = bn2g; p.p2 = bn2b;
    run_tg(2, 1, p, BB*SN, 1);
    // 12. sigma, e, sq
    k_sigma_e<<<BB*SN, 256>>>(ow, ob);
    // 13. W = exp(-(d2/768)/2)  (M=512, N=512, K=768, z=b)
    p.A = p_e; p.sA1 = (long)SN*DF; p.lda = DF;
    p.B = p_e; p.sB1 = (long)SN*DF; p.ldb = DF;
    p.C = p_w; p.sC1 = (long)SN*SN; p.ldc = SN;
    p.N = SN; p.K = DF; p.p0 = p_sq; p.sP0 = SN;
    run_tg(3, 1, p, SN, BB);
    // 14. top-k mask, symmetrize+degree, build A and Chebyshev X1
    k_topk<<<BB*SN/4, 128>>>();
    k_degree<<<BB*SN, 256>>>();
    k_buildA<<<(BB*SN*SN + 255)/256, 256>>>(alpha);
    // 15. Chebyshev-composed scaled Newton: X <- gamma_k * X(2I - AX), 5 iters.
    //     Residual = 1/T_{2^{k+1}}(mu): after 5 iters 1/T_64 ~ 2.3e-4 (measured
    //     rel_err 2.40e-4 at R13) -- 4x under the 1e-3 gate.
    float* Xc = p_Xa; float* Xn = p_Xb;
    for (int it = 0; it < 5; it++) {
        // T = A @ Xc
        p.A = p_A;  p.sA1 = (long)SN*SN; p.sA2 = 0; p.lda = SN;
        p.B = Xc;   p.sB1 = (long)SN*SN; p.sB2 = 0; p.ldb = SN;
        p.C = p_T;  p.sC1 = (long)SN*SN; p.ldc = SN;
        p.N = SN; p.K = SN; p.scale = 1.f; p.p0 = 0; p.sP0 = 0; p.iter = it;
        run_tg(0, 0, p, SN, BB);
        // Xn = gamma_it * (2*Xc - Xc @ T)
        p.A = Xc; p.B = p_T; p.C = Xn;
        p.p0 = Xc; p.sP0 = (long)SN*SN;
        run_tg(4, 0, p, SN, BB);
        float* t = Xc; Xc = Xn; Xn = t;
    }
    // 16. out = prop @ one_hot(labels): zero + scatter (prop symmetric)
    cudaMemsetAsync(out, 0, (size_t)out_size * sizeof(float));
    dim3 sg(SN/128, SN, BB);
    k_scatter<<<sg, 128>>>(lab, Xc, out);
}

// round 16
// speedup vs baseline: 1.0137x; 1.0137x over previous
#include <cuda_runtime.h>
#include <math.h>

#define BB 8
#define SN 512
#define SIDX 256
#define DF 768
#define NH 12
#define HD 64
#define PJ 256
#define HID 128
#define VOC 16384
#define KTOP 20
#define KVN 1536

#define ASTR 20     // A smem row stride (m-major, 16 k + pad)
#define BSTR1 20    // B smem row stride, BT=1 ([n][k])
#define BSTR0 68    // B smem row stride, BT=0 ([k][n])

// ---------------- scratch (static device globals; no allocations) ------------
__device__ float g_emb[BB*SN*DF];
__device__ float g_q  [BB*SIDX*DF];
__device__ float g_kv [BB*SN*KVN];
__device__ float g_s  [BB*NH*SIDX*SN];
__device__ float g_o  [BB*SIDX*DF];
__device__ float g_mha[BB*SIDX*DF];
__device__ float g_xp [BB*SN*PJ];
__device__ float g_h1 [BB*SN*HID];
__device__ float g_h2 [BB*SN*HID];
__device__ float g_e  [BB*SN*DF];
__device__ float g_sq [BB*SN];
__device__ float g_w  [BB*SN*SN];
__device__ unsigned char g_mk [BB*SN*SN];
__device__ unsigned char g_mkT[BB*SN*SN];
__device__ float g_dsi[BB*SN];
__device__ float g_A  [BB*SN*SN];
__device__ float g_Xa [BB*SN*SN];
__device__ float g_Xb [BB*SN*SN];
__device__ float g_T  [BB*SN*SN];
__device__ float g_w1r[HID*768];
__device__ float g_w2r[HID*384];

// ---------------- unified tensor-core GEMM (split-tf32, cp.async) -------------
// R14 tiling: 128 thr, 4 warps (2x2), warp tile 64x32 (2:1 MMA:LDS).
// IMS!=0: implicit im2col on A (conv path). A is [B*512, cin] activations;
// logical A[m,k]: kern=k>>IMS, ci=k&(cin-1), src=(m&511)+kern-1; rows outside
// [0,512) zero-filled via cp.async register src-size.
// C = epi( A(MxK) * op(B) ) ; BT=1: B is [N,K] (C=A*B^T), BT=0: B is [K,N]
// CTA tile 128x64, K-slab 16. Requires M%128==0, N%64==0, K%16==0.
// EPI: 0 scale  1 +bias  2 conv+bn+relu  3 gaussian-W
//      4 scaled-newton: C = gamma_iter*(2*X - acc), Chebyshev-composed gamma.
struct GemmP {
    const float* A; const float* B; float* C;
    int N, K, lda, ldb, ldc, zdiv;
    long sA1, sA2, sB1, sB2, sC1, sC2, sP0;
    float scale;
    const float* p0; const float* p1; const float* p2;
    const float* alp; int iter;
};

__device__ __forceinline__ float tf32hi(float x) {
    return __uint_as_float(__float_as_uint(x) & 0xFFFFE000u);
}
__device__ __forceinline__ void mma8(float* d, const unsigned* a, const unsigned* b) {
    asm volatile("mma.sync.aligned.m16n8k8.row.col.f32.tf32.tf32.f32 "
        "{%0,%1,%2,%3}, {%4,%5,%6,%7}, {%8,%9}, {%0,%1,%2,%3};"
        : "+f"(d[0]), "+f"(d[1]), "+f"(d[2]), "+f"(d[3])
        : "r"(a[0]), "r"(a[1]), "r"(a[2]), "r"(a[3]), "r"(b[0]), "r"(b[1]));
}
#define CPA16(dst, src) asm volatile("cp.async.ca.shared.global [%0], [%1], 16;" \
                                     :: "r"(dst), "l"(src))
#define CPA16Z(dst, src, ok) asm volatile("{\n\t.reg .pred p;\n\t" \
        "setp.ne.u32 p, %2, 0;\n\t.reg .b32 q;\n\tselp.b32 q, 16, 0, p;\n\t" \
        "cp.async.ca.shared.global [%0], [%1], 16, q;\n\t}" \
        :: "r"(dst), "l"(src), "r"(ok))
#define CPCOMMIT()      asm volatile("cp.async.commit_group;")
#define CPWAIT0()       asm volatile("cp.async.wait_group 0;" ::: "memory")

template<int EPI, int BT, int IMS>
__global__ void __launch_bounds__(128, 2) tgemm_k(GemmP p) {
    __shared__ float As[2][128*ASTR];
    __shared__ float Bs[2][1280];
    int z  = blockIdx.z;
    int zb = z / p.zdiv, zr = z % p.zdiv;
    const float* Ap = p.A + zb * p.sA1 + (long)zr * p.sA2;
    const float* Bp = p.B + zb * p.sB1 + (long)zr * p.sB2;
    float*       Cp = p.C + zb * p.sC1 + (long)zr * p.sC2;
    int bm = blockIdx.y * 128, bn = blockIdx.x * 64;
    int tid = threadIdx.x;
    int warp = tid >> 5, lane = tid & 31;
    int g = lane >> 2, t = lane & 3;
    int m0 = (warp >> 1) * 64, n0 = (warp & 1) * 32;

    // loader coords (128 threads)
    int ar  = tid >> 2, akq = (tid & 3) * 4;   // A: 4 f4/thread, rows ar+f*32
    int bkr = tid >> 4, bnc = (tid & 15) * 4;  // B BT=0: 2 f4/thread
    unsigned sA[2] = { (unsigned)__cvta_generic_to_shared(&As[0][0]),
                       (unsigned)__cvta_generic_to_shared(&As[1][0]) };
    unsigned sB[2] = { (unsigned)__cvta_generic_to_shared(&Bs[0][0]),
                       (unsigned)__cvta_generic_to_shared(&Bs[1][0]) };

    float acc[4][4][4];
#pragma unroll
    for (int i = 0; i < 4; i++)
#pragma unroll
        for (int j = 0; j < 4; j++)
#pragma unroll
            for (int r = 0; r < 4; r++) acc[i][j][r] = 0.f;

    int nSlab = p.K >> 4;

    auto issue = [&](int it) {
        int buf = it & 1;
        int k0 = it << 4;
#pragma unroll
        for (int f = 0; f < 4; f++) {
            if (IMS) {          // implicit im2col (conv path)
                int row = bm + ar + f*32;
                int l = row & 511;
                int k = k0 + akq;
                int kern = k >> IMS;
                int ci = k & ((1 << IMS) - 1);
                int src = l + kern - 1;
                unsigned ok = ((unsigned)src < 512u) ? 1u : 0u;
                int sc = ok ? src : 0;
                const float* gp = Ap + ((long)((row & ~511) + sc) << IMS) + ci;
                CPA16Z(sA[buf] + (unsigned)(((ar + f*32)*ASTR + akq) * 4), gp, ok);
            } else {
                CPA16(sA[buf] + (unsigned)(((ar + f*32)*ASTR + akq) * 4),
                      Ap + (long)(bm + ar + f*32) * p.lda + k0 + akq);
            }
        }
        if (BT) {
#pragma unroll
            for (int f = 0; f < 2; f++)
                CPA16(sB[buf] + (unsigned)(((ar + f*32)*BSTR1 + akq) * 4),
                      Bp + (long)(bn + ar + f*32) * p.ldb + k0 + akq);
        } else {
#pragma unroll
            for (int f = 0; f < 2; f++)
                CPA16(sB[buf] + (unsigned)(((bkr + f*8)*BSTR0 + bnc) * 4),
                      Bp + (long)(k0 + bkr + f*8) * p.ldb + bn + bnc);
        }
        CPCOMMIT();
    };

    issue(0);
    for (int it = 0; it < nSlab; it++) {
        CPWAIT0();
        __syncthreads();
        if (it + 1 < nSlab) issue(it + 1);
        const float* as = As[it & 1];
        const float* bs = Bs[it & 1];
#pragma unroll
        for (int ks = 0; ks < 2; ks++) {
            int kb = ks * 8;
            unsigned ah[4][4], al[4][4];
#pragma unroll
            for (int i = 0; i < 4; i++) {
                int mb = m0 + i*16;
                float r0 = as[(mb + g    )*ASTR + kb + t    ];
                float r1 = as[(mb + 8 + g)*ASTR + kb + t    ];
                float r2 = as[(mb + g    )*ASTR + kb + t + 4];
                float r3 = as[(mb + 8 + g)*ASTR + kb + t + 4];
                float h0 = tf32hi(r0), h1 = tf32hi(r1), h2 = tf32hi(r2), h3 = tf32hi(r3);
                ah[i][0] = __float_as_uint(h0); al[i][0] = __float_as_uint(r0 - h0);
                ah[i][1] = __float_as_uint(h1); al[i][1] = __float_as_uint(r1 - h1);
                ah[i][2] = __float_as_uint(h2); al[i][2] = __float_as_uint(r2 - h2);
                ah[i][3] = __float_as_uint(h3); al[i][3] = __float_as_uint(r3 - h3);
            }
            unsigned bh[4][2], bl[4][2];
#pragma unroll
            for (int j = 0; j < 4; j++) {
                int nb = n0 + j*8 + g;
                float r0, r1;
                if (BT) { r0 = bs[nb*BSTR1 + kb + t];   r1 = bs[nb*BSTR1 + kb + t + 4]; }
                else    { r0 = bs[(kb + t)*BSTR0 + nb]; r1 = bs[(kb + t + 4)*BSTR0 + nb]; }
                float h0 = tf32hi(r0), h1 = tf32hi(r1);
                bh[j][0] = __float_as_uint(h0); bl[j][0] = __float_as_uint(r0 - h0);
                bh[j][1] = __float_as_uint(h1); bl[j][1] = __float_as_uint(r1 - h1);
            }
#pragma unroll
            for (int i = 0; i < 4; i++)
#pragma unroll
                for (int j = 0; j < 4; j++) {
                    mma8(acc[i][j], ah[i], bh[j]);
                    mma8(acc[i][j], ah[i], bl[j]);
                    mma8(acc[i][j], al[i], bh[j]);
                }
        }
        __syncthreads();
    }

    const float* P0 = p.p0;
    if (EPI == 3 || EPI == 4) P0 = p.p0 + zb * p.sP0;
    float gam = 1.f;
    if (EPI == 4) {
        float mu = (1.f + 1e-6f) / p.alp[0];
        float tt = 2.f*mu*mu - 1.f;               // t_1 = T_2(mu)
        for (int q = 0; q < p.iter; q++) tt = 2.f*tt*tt - 1.f;
        float tg = 2.f*tt*tt;
        gam = tg / (tg - 1.f);
    }
#pragma unroll
    for (int i = 0; i < 4; i++)
#pragma unroll
        for (int j = 0; j < 4; j++) {
            int m  = bm + m0 + i*16 + g;
            int n  = bn + n0 + j*8 + 2*t;
            float v0 = acc[i][j][0], v1 = acc[i][j][1];
            float v2 = acc[i][j][2], v3 = acc[i][j][3];
            if (EPI == 0) {
                v0 *= p.scale; v1 *= p.scale; v2 *= p.scale; v3 *= p.scale;
            } else if (EPI == 1) {
                v0 += p.p0[n]; v1 += p.p0[n+1]; v2 += p.p0[n]; v3 += p.p0[n+1];
            } else if (EPI == 2) {
                float g0 = 0.9999950000125f * p.p1[n],   b0 = p.p2[n];
                float g1 = 0.9999950000125f * p.p1[n+1], b1 = p.p2[n+1];
                v0 = fmaxf((v0 + p.p0[n])   * g0 + b0, 0.f);
                v1 = fmaxf((v1 + p.p0[n+1]) * g1 + b1, 0.f);
                v2 = fmaxf((v2 + p.p0[n])   * g0 + b0, 0.f);
                v3 = fmaxf((v3 + p.p0[n+1]) * g1 + b1, 0.f);
            } else if (EPI == 3) {
                float sm0 = P0[m], sm8 = P0[m+8], sn0 = P0[n], sn1 = P0[n+1];
                v0 = expf(-fmaxf(sm0 + sn0 - 2.f*v0, 0.f) * (1.f/1536.f));
                v1 = expf(-fmaxf(sm0 + sn1 - 2.f*v1, 0.f) * (1.f/1536.f));
                v2 = expf(-fmaxf(sm8 + sn0 - 2.f*v2, 0.f) * (1.f/1536.f));
                v3 = expf(-fmaxf(sm8 + sn1 - 2.f*v3, 0.f) * (1.f/1536.f));
            } else if (EPI == 4) {
                v0 = gam * (2.f * P0[(long)m*p.ldc + n]       - v0);
                v1 = gam * (2.f * P0[(long)m*p.ldc + n + 1]   - v1);
                v2 = gam * (2.f * P0[(long)(m+8)*p.ldc + n]   - v2);
                v3 = gam * (2.f * P0[(long)(m+8)*p.ldc + n+1] - v3);
            }
            Cp[(long)m*p.ldc + n]       = v0;
            Cp[(long)m*p.ldc + n + 1]   = v1;
            Cp[(long)(m+8)*p.ldc + n]   = v2;
            Cp[(long)(m+8)*p.ldc + n+1] = v3;
        }
}

// ---------------- elementwise / reduction kernels ----------------------------
__global__ void k_build_emb(const float* ge, const float* ue) {
    long i = (long)blockIdx.x * blockDim.x + threadIdx.x;
    if (i >= (long)BB*SN*DF) return;
    int d = i % DF; long bn = i / DF; int n = bn % SN; int b = (int)(bn / SN);
    float x = (n < SIDX) ? ge[((long)b*SIDX + n)*DF + d]
                         : ue[((long)b*SIDX + (n - SIDX))*DF + d];
    int half = d >> 1;
    float freq = expf((float)(2*half) * (-9.210340371976184f/768.f));
    float arg = (float)n * freq;
    float pe = (d & 1) ? cosf(arg) : sinf(arg);
    g_emb[i] = x + pe;
}

__global__ void k_softmax() {
    long row = blockIdx.x;
    float* r = g_s + row * SN;
    int tid = threadIdx.x;
    __shared__ float red[256];
    float v0 = r[tid], v1 = r[tid+256];
    red[tid] = fmaxf(v0, v1); __syncthreads();
    for (int s = 128; s > 0; s >>= 1) { if (tid < s) red[tid] = fmaxf(red[tid], red[tid+s]); __syncthreads(); }
    float m = red[0]; __syncthreads();
    float e0 = expf(v0 - m), e1 = expf(v1 - m);
    red[tid] = e0 + e1; __syncthreads();
    for (int s = 128; s > 0; s >>= 1) { if (tid < s) red[tid] += red[tid+s]; __syncthreads(); }
    float inv = 1.f / red[0];
    r[tid] = e0 * inv; r[tid+256] = e1 * inv;
}

__global__ void k_addln(const float* lng, const float* lnb) {
    int row = blockIdx.x;
    int b = row >> 8, rr = row & 255;
    float*       u  = g_emb + ((long)b*SN + SIDX + rr) * DF;
    const float* mh = g_mha + ((long)b*SIDX + rr) * DF;
    int tid = threadIdx.x;
    __shared__ float red[256];
    float x[3];
#pragma unroll
    for (int t = 0; t < 3; t++) x[t] = u[tid + t*256] + mh[tid + t*256];
    red[tid] = x[0] + x[1] + x[2]; __syncthreads();
    for (int s = 128; s > 0; s >>= 1) { if (tid < s) red[tid] += red[tid+s]; __syncthreads(); }
    float mean = red[0] * (1.f/768.f); __syncthreads();
    float vs = 0.f;
#pragma unroll
    for (int t = 0; t < 3; t++) { float d = x[t] - mean; vs += d*d; }
    red[tid] = vs; __syncthreads();
    for (int s = 128; s > 0; s >>= 1) { if (tid < s) red[tid] += red[tid+s]; __syncthreads(); }
    float inv = rsqrtf(red[0] * (1.f/768.f) + 1e-5f);
#pragma unroll
    for (int t = 0; t < 3; t++) {
        int d = tid + t*256;
        u[d] = (x[t] - mean) * inv * lng[d] + lnb[d];
    }
}

__global__ void k_wprep(const float* c1w, const float* c2w) {
    int i = blockIdx.x * blockDim.x + threadIdx.x;
    if (i < 128*768) {
        int c = i / 768, r = i % 768, k = r / 256, ci = r % 256;
        g_w1r[i] = c1w[(c*256 + ci)*3 + k];
    } else if (i < 128*768 + 128*384) {
        int j = i - 128*768;
        int c = j / 384, r = j % 384, k = r / 128, ci = r % 128;
        g_w2r[j] = c2w[(c*128 + ci)*3 + k];
    }
}

__global__ void k_sigma_e(const float* ow, const float* ob) {
    int row = blockIdx.x;
    int tid = threadIdx.x;
    __shared__ float red[256];
    float part = (tid < HID) ? g_h2[(long)row*HID + tid] * ow[tid] : 0.f;
    red[tid] = part; __syncthreads();
    for (int s = 128; s > 0; s >>= 1) { if (tid < s) red[tid] += red[tid+s]; __syncthreads(); }
    float sig = red[0] + ob[0]; __syncthreads();
    float inv = 1.f / (sig + 1e-6f);
    const float* er = g_emb + (long)row*DF;
    float*       eo = g_e   + (long)row*DF;
    float ss = 0.f;
#pragma unroll
    for (int t = 0; t < 3; t++) {
        float e = er[tid + t*256] * inv;
        eo[tid + t*256] = e;
        ss += e*e;
    }
    red[tid] = ss; __syncthreads();
    for (int s = 128; s > 0; s >>= 1) { if (tid < s) red[tid] += red[tid+s]; __syncthreads(); }
    if (tid == 0) g_sq[row] = red[0];
}

// top-k mask; also writes transposed mask (g_mkT pre-zeroed by memset).
__global__ void k_topk() {
    int row = blockIdx.x * (blockDim.x >> 5) + (threadIdx.x >> 5);
    int lane = threadIdx.x & 31;
    if (row >= BB*SN) return;
    int b = row >> 9, rr = row & 511;
    const float* w = g_w + (long)row * SN;
    unsigned char* mk = g_mk + (long)row * SN;
    for (int j = lane; j < SN/4; j += 32) ((unsigned int*)mk)[j] = 0u;
    __syncwarp();
    float v[16];
#pragma unroll
    for (int j = 0; j < 16; j++) v[j] = w[lane + j*32];
    for (int t = 0; t < KTOP; t++) {
        float bm = -1.f; int bj = 0;
#pragma unroll
        for (int j = 0; j < 16; j++) {
            if (v[j] > bm) { bm = v[j]; bj = j; }
        }
        int bidx = lane + bj*32;
#pragma unroll
        for (int s = 16; s > 0; s >>= 1) {
            float om = __shfl_xor_sync(0xffffffffu, bm, s);
            int oi = __shfl_xor_sync(0xffffffffu, bidx, s);
            if (om > bm || (om == bm && oi < bidx)) { bm = om; bidx = oi; }
        }
        if ((bidx & 31) == lane) v[bidx >> 5] = -1.f;
        if (lane == 0) {
            mk[bidx] = 1;
            g_mkT[((long)(b*SN + bidx))*SN + rr] = 1;
        }
        __syncwarp();
    }
}

// symmetrize + degree: both mask reads now coalesced (mk row | mkT row).
__global__ void k_degree() {
    int row = blockIdx.x;
    float* w = g_w + (long)row*SN;
    const unsigned char* mrow  = g_mk  + (long)row*SN;
    const unsigned char* mtrow = g_mkT + (long)row*SN;
    int tid = threadIdx.x;
    __shared__ float red[256];
    float s = 0.f;
    for (int m = tid; m < SN; m += 256) {
        int on = mrow[m] | mtrow[m];
        float val = on ? w[m] : 0.f;
        w[m] = val;
        s += val;
    }
    red[tid] = s; __syncthreads();
    for (int st = 128; st > 0; st >>= 1) { if (tid < st) red[tid] += red[tid+st]; __syncthreads(); }
    if (tid == 0) g_dsi[row] = rsqrtf(red[0] + 1e-6f);
}

// Build A = (1+eps)I - alpha*S, and Chebyshev-optimal X1 = c0*I + c1*A.
__global__ void k_buildA(const float* alpha) {
    long i = (long)blockIdx.x * blockDim.x + threadIdx.x;
    if (i >= (long)BB*SN*SN) return;
    int m = (int)(i % SN); long t = i / SN; int n = (int)(t % SN); int b = (int)(t / SN);
    float a = alpha[0];
    float Sg = 2.f * (1.f + 1e-6f);
    float Dg = 2.f * a;
    float den = 2.f * Sg * Sg - Dg * Dg;
    float c0 = 8.f * Sg / den, c1 = -8.f / den;
    float s = g_dsi[b*SN+n] * g_w[i] * g_dsi[b*SN+m];
    float A = ((n==m) ? 1.f + 1e-6f : 0.f) - a * s;
    g_A[i] = A;
    g_Xa[i] = ((n==m) ? c0 : 0.f) + c1 * A;
}

__global__ void k_scatter(const int* labels, const float* X, float* out) {
    int b = blockIdx.z;
    int m = blockIdx.y;
    int n = blockIdx.x * 128 + threadIdx.x;
    int lab = labels[b*SN + m];
    if (lab >= VOC) return;
    float v = X[((long)(b*SN + m))*SN + n];    // symmetric: prop[b,n,m]
    atomicAdd(out + ((long)(b*SN + n))*VOC + lab, v);
}

// ---------------- host side ---------------------------------------------------
static void run_tg(int epi, int bt, const GemmP& p, int M, int Z) {
    dim3 g(p.N / 64, M / 128, Z);
    dim3 b(128);
    if (epi == 0 && bt == 1) tgemm_k<0,1,0><<<g,b>>>(p);
    else if (epi == 0 && bt == 0) tgemm_k<0,0,0><<<g,b>>>(p);
    else if (epi == 1 && bt == 1) tgemm_k<1,1,0><<<g,b>>>(p);
    else if (epi == 3 && bt == 1) tgemm_k<3,1,0><<<g,b>>>(p);
    else if (epi == 4 && bt == 0) tgemm_k<4,0,0><<<g,b>>>(p);
}

static void run_conv(const GemmP& p, int M, int cshift) {
    dim3 g(p.N / 64, M / 128, 1);
    dim3 b(128);
    if (cshift == 8) tgemm_k<2,1,8><<<g,b>>>(p);
    else             tgemm_k<2,1,7><<<g,b>>>(p);
}

extern "C" void kernel_launch(void* const* d_in, const int* in_sizes, int n_in,
                              void* d_out, int out_size) {
    const float* ge    = (const float*)d_in[0];
    const float* ue    = (const float*)d_in[1];
    const float* hs    = (const float*)d_in[2];
    const int*   lab   = (const int*)  d_in[3];
    const float* inw   = (const float*)d_in[4];
    const float* inb   = (const float*)d_in[5];
    const float* outw  = (const float*)d_in[6];
    const float* outb  = (const float*)d_in[7];
    const float* lng   = (const float*)d_in[8];
    const float* lnb   = (const float*)d_in[9];
    const float* pw    = (const float*)d_in[10];
    const float* pb    = (const float*)d_in[11];
    const float* c1w   = (const float*)d_in[12];
    const float* c1b   = (const float*)d_in[13];
    const float* bn1g  = (const float*)d_in[14];
    const float* bn1b  = (const float*)d_in[15];
    const float* c2w   = (const float*)d_in[16];
    const float* c2b   = (const float*)d_in[17];
    const float* bn2g  = (const float*)d_in[18];
    const float* bn2b  = (const float*)d_in[19];
    const float* ow    = (const float*)d_in[20];
    const float* ob    = (const float*)d_in[21];
    const float* alpha = (const float*)d_in[22];
    float* out = (float*)d_out;

    void* vp;
    cudaGetSymbolAddress(&vp, g_emb); float* p_emb = (float*)vp;
    cudaGetSymbolAddress(&vp, g_q);   float* p_q   = (float*)vp;
    cudaGetSymbolAddress(&vp, g_kv);  float* p_kv  = (float*)vp;
    cudaGetSymbolAddress(&vp, g_s);   float* p_s   = (float*)vp;
    cudaGetSymbolAddress(&vp, g_o);   float* p_o   = (float*)vp;
    cudaGetSymbolAddress(&vp, g_mha); float* p_mha = (float*)vp;
    cudaGetSymbolAddress(&vp, g_xp);  float* p_xp  = (float*)vp;
    cudaGetSymbolAddress(&vp, g_h1);  float* p_h1  = (float*)vp;
    cudaGetSymbolAddress(&vp, g_h2);  float* p_h2  = (float*)vp;
    cudaGetSymbolAddress(&vp, g_e);   float* p_e   = (float*)vp;
    cudaGetSymbolAddress(&vp, g_sq);  float* p_sq  = (float*)vp;
    cudaGetSymbolAddress(&vp, g_w);   float* p_w   = (float*)vp;
    cudaGetSymbolAddress(&vp, g_mkT); unsigned char* p_mkT = (unsigned char*)vp;
    cudaGetSymbolAddress(&vp, g_A);   float* p_A   = (float*)vp;
    cudaGetSymbolAddress(&vp, g_Xa);  float* p_Xa  = (float*)vp;
    cudaGetSymbolAddress(&vp, g_Xb);  float* p_Xb  = (float*)vp;
    cudaGetSymbolAddress(&vp, g_T);   float* p_T   = (float*)vp;
    cudaGetSymbolAddress(&vp, g_w1r); float* p_w1r = (float*)vp;
    cudaGetSymbolAddress(&vp, g_w2r); float* p_w2r = (float*)vp;

    // 1. emb = concat + PE ; weight reshapes ; zero transposed mask
    k_build_emb<<<(BB*SN*DF + 255)/256, 256>>>(ge, ue);
    k_wprep<<<(128*768 + 128*384)/256, 256>>>(c1w, c2w);
    cudaMemsetAsync(p_mkT, 0, (size_t)BB*SN*SN);

    GemmP p;
    p.zdiv = 1; p.scale = 1.f;
    p.sA1 = p.sA2 = p.sB1 = p.sB2 = p.sC1 = p.sC2 = p.sP0 = 0;
    p.p0 = p.p1 = p.p2 = 0; p.alp = alpha; p.iter = 0;

    // 2. Q = u @ wq^T + bq   (batched over b, M=256 per batch)
    p.A = p_emb + SIDX*DF; p.sA1 = (long)SN*DF; p.lda = DF;
    p.B = inw;             p.ldb = DF;  p.sB1 = 0;
    p.C = p_q;  p.sC1 = (long)SIDX*DF; p.ldc = DF;
    p.N = DF; p.K = DF; p.p0 = inb;
    run_tg(1, 1, p, SIDX, BB);
    // 3. [K|V] = hs @ [wk;wv]^T + [bk;bv]  -- fused, N=1536, M=4096
    p.A = hs; p.sA1 = 0; p.lda = DF;
    p.B = inw + DF*DF;  p.C = p_kv; p.sC1 = 0; p.ldc = KVN;
    p.N = KVN; p.p0 = inb + DF;
    run_tg(1, 1, p, BB*SN, 1);

    // 4. scores = Q K^T / 8  (z = b*h, K=64); K lives in g_kv cols [0,768)
    p.zdiv = NH;
    p.A = p_q;  p.sA1 = (long)SIDX*DF;  p.sA2 = HD; p.lda = DF;
    p.B = p_kv; p.sB1 = (long)SN*KVN;   p.sB2 = HD; p.ldb = KVN;
    p.C = p_s;  p.sC1 = (long)NH*SIDX*SN; p.sC2 = (long)SIDX*SN; p.ldc = SN;
    p.N = SN; p.K = HD; p.scale = 0.125f;
    run_tg(0, 1, p, SIDX, BB*NH);
    // 5. softmax
    k_softmax<<<BB*NH*SIDX, 256>>>();
    // 6. o = attn @ V  (BT=0, N=64); V lives in g_kv cols [768,1536)
    p.A = p_s;  p.sA1 = (long)NH*SIDX*SN; p.sA2 = (long)SIDX*SN; p.lda = SN;
    p.B = p_kv + DF; p.sB1 = (long)SN*KVN; p.sB2 = HD; p.ldb = KVN;
    p.C = p_o;  p.sC1 = (long)SIDX*DF; p.sC2 = HD; p.ldc = DF;
    p.N = HD; p.K = SN; p.scale = 1.f;
    run_tg(0, 0, p, SIDX, BB*NH);
    // 7. mha = o @ out_w^T + out_b  (M=2048)
    p.zdiv = 1; p.sA1 = p.sA2 = p.sB1 = p.sB2 = p.sC1 = p.sC2 = 0;
    p.A = p_o; p.lda = DF; p.B = outw; p.ldb = DF;
    p.C = p_mha; p.ldc = DF; p.N = DF; p.K = DF; p.p0 = outb;
    run_tg(1, 1, p, BB*SIDX, 1);
    // 8. u = LN(u + mha)
    k_addln<<<BB*SIDX, 256>>>(lng, lnb);
    // 9. xp = emb @ proj_w^T + proj_b  (M=4096, N=256)
    p.A = p_emb; p.lda = DF; p.B = pw; p.ldb = DF;
    p.C = p_xp; p.ldc = PJ; p.N = PJ; p.K = DF; p.p0 = pb;
    run_tg(1, 1, p, BB*SN, 1);
    // 10. conv1 + bn + relu  (implicit im2col, cin=256: IMS=8; K=768)
    p.A = p_xp; p.lda = PJ; p.B = p_w1r; p.ldb = 768;
    p.C = p_h1; p.ldc = HID; p.N = HID; p.K = 768;
    p.p0 = c1b; p.p1 = bn1g; p.p2 = bn1b;
    run_conv(p, BB*SN, 8);
    // 11. conv2 + bn + relu  (implicit im2col, cin=128: IMS=7; K=384)
    p.A = p_h1; p.lda = HID; p.B = p_w2r; p.ldb = 384;
    p.C = p_h2; p.ldc = HID; p.N = HID; p.K = 384;
    p.p0 = c2b; p.p1 = bn2g; p.p2 = bn2b;
    run_conv(p, BB*SN, 7);
    // 12. sigma, e, sq
    k_sigma_e<<<BB*SN, 256>>>(ow, ob);
    // 13. W = exp(-(d2/768)/2)  (M=512, N=512, K=768, z=b)
    p.A = p_e; p.sA1 = (long)SN*DF; p.lda = DF;
    p.B = p_e; p.sB1 = (long)SN*DF; p.ldb = DF;
    p.C = p_w; p.sC1 = (long)SN*SN; p.ldc = SN;
    p.N = SN; p.K = DF; p.p0 = p_sq; p.sP0 = SN;
    run_tg(3, 1, p, SN, BB);
    // 14. top-k mask (+ transposed mask), symmetrize+degree, build A and X1
    k_topk<<<BB*SN/4, 128>>>();
    k_degree<<<BB*SN, 256>>>();
    k_buildA<<<(BB*SN*SN + 255)/256, 256>>>(alpha);
    // 15. Chebyshev-composed scaled Newton: X <- gamma_k * X(2I - AX), 5 iters.
    //     Residual = 1/T_64 ~ 2.3e-4 (measured 2.40e-4 at R13/R14).
    float* Xc = p_Xa; float* Xn = p_Xb;
    for (int it = 0; it < 5; it++) {
        // T = A @ Xc
        p.A = p_A;  p.sA1 = (long)SN*SN; p.sA2 = 0; p.lda = SN;
        p.B = Xc;   p.sB1 = (long)SN*SN; p.sB2 = 0; p.ldb = SN;
        p.C = p_T;  p.sC1 = (long)SN*SN; p.ldc = SN;
        p.N = SN; p.K = SN; p.scale = 1.f; p.p0 = 0; p.sP0 = 0; p.iter = it;
        run_tg(0, 0, p, SN, BB);
        // Xn = gamma_it * (2*Xc - Xc @ T)
        p.A = Xc; p.B = p_T; p.C = Xn;
        p.p0 = Xc; p.sP0 = (long)SN*SN;
        run_tg(4, 0, p, SN, BB);
        float* t = Xc; Xc = Xn; Xn = t;
    }
    // 16. out = prop @ one_hot(labels): zero + scatter (prop symmetric)
    cudaMemsetAsync(out, 0, (size_t)out_size * sizeof(float));
    dim3 sg(SN/128, SN, BB);
    k_scatter<<<sg, 128>>>(lab, Xc, out);
}